// round 13
// baseline (speedup 1.0000x reference)
#include <cuda_runtime.h>
#include <cuda_bf16.h>
#include <cstdint>

#define BATCH 4
#define NQ    4096
#define NK    4096
#define DIM   256
#define SCALE 0.17677669529663687f   // (256/8)^-0.5

#define BM 128
#define BN 64
#define NBLK (NK / BN)
#define THREADS 256

// device-global scratch (no allocations allowed)
__device__ __nv_bfloat16 g_Qn[BATCH * NQ * DIM];
__device__ __nv_bfloat16 g_Kn[BATCH * NK * DIM];
__device__ __nv_bfloat16 g_Vb[BATCH * NK * DIM];
__device__ float         g_Vsum[BATCH * DIM];

// smem layout (bytes) — XOR-swizzled tiles, 512B rows (no padding)
#define SQ_OFF  0u            // Q 128 x 256 bf16 = 65536
#define SK0_OFF 65536u        // K/V tiles 64 x 256 bf16 = 32768 each
#define SV0_OFF 98304u
#define SK1_OFF 131072u
#define SV1_OFF 163840u
#define SP_OFF  196608u       // P 128 x 64 bf16 = 16384 (128B rows)
#define SVS_OFF 212992u       // float[256]
#define SL_OFF  214016u       // float[2][128]
static const int SMEM_BYTES = 215040;

// ---------------------------------------------------------------- helpers
__device__ __forceinline__ uint32_t smem_u32(const void* p) {
    return (uint32_t)__cvta_generic_to_shared(p);
}

#define LDSM_X4(r0, r1, r2, r3, addr)                                              \
    asm volatile("ldmatrix.sync.aligned.m8n8.x4.shared.b16 {%0,%1,%2,%3},[%4];"    \
                 : "=r"(r0), "=r"(r1), "=r"(r2), "=r"(r3) : "r"(addr))

#define LDSM_X4_T(r0, r1, r2, r3, addr)                                                 \
    asm volatile("ldmatrix.sync.aligned.m8n8.x4.trans.shared.b16 {%0,%1,%2,%3},[%4];"   \
                 : "=r"(r0), "=r"(r1), "=r"(r2), "=r"(r3) : "r"(addr))

#define MMA16816(d, a0, a1, a2, a3, b0, b1)                                        \
    asm volatile("mma.sync.aligned.m16n8k16.row.col.f32.bf16.bf16.f32 "            \
                 "{%0,%1,%2,%3},{%4,%5,%6,%7},{%8,%9},{%0,%1,%2,%3};"              \
                 : "+f"(d[0]), "+f"(d[1]), "+f"(d[2]), "+f"(d[3])                  \
                 : "r"(a0), "r"(a1), "r"(a2), "r"(a3), "r"(b0), "r"(b1))

__device__ __forceinline__ void cp16(uint32_t s, const void* g) {
    asm volatile("cp.async.cg.shared.global [%0], [%1], 16;" :: "r"(s), "l"(g));
}
#define CP_COMMIT() asm volatile("cp.async.commit_group;" ::: "memory")
#define CP_WAIT(n)  asm volatile("cp.async.wait_group %0;" :: "n"(n) : "memory")
#define BAR_SYNC(id, cnt) asm volatile("bar.sync %0, %1;" :: "r"(id), "r"(cnt) : "memory")

// ---------------------------------------------------------------- prep kernels
__global__ void zero_vsum_kernel() { g_Vsum[threadIdx.x] = 0.0f; }

__global__ void vprep_kernel(const float* __restrict__ v) {
    int b = blockIdx.y, chunk = blockIdx.x, d = threadIdx.x;
    size_t base = ((size_t)b * NK + (size_t)chunk * 128) * DIM + d;
    float sum = 0.0f;
    for (int r = 0; r < 128; r++) {
        float x = v[base + (size_t)r * DIM];
        sum += x;
        g_Vb[base + (size_t)r * DIM] = __float2bfloat16(x);
    }
    atomicAdd(&g_Vsum[b * DIM + d], sum);
}

__global__ void normalize_kernel(const float* __restrict__ q, const float* __restrict__ k) {
    int gw = (blockIdx.x * blockDim.x + threadIdx.x) >> 5;
    int lane = threadIdx.x & 31;
    const float* src;
    __nv_bfloat16* dst;
    int row;
    if (gw < BATCH * NQ) { src = q; dst = g_Qn; row = gw; }
    else                 { src = k; dst = g_Kn; row = gw - BATCH * NQ; }

    const float4* p = (const float4*)(src + (size_t)row * DIM);
    float4 v0 = p[lane];
    float4 v1 = p[lane + 32];
    float ss = v0.x * v0.x + v0.y * v0.y + v0.z * v0.z + v0.w * v0.w
             + v1.x * v1.x + v1.y * v1.y + v1.z * v1.z + v1.w * v1.w;
#pragma unroll
    for (int off = 16; off > 0; off >>= 1) ss += __shfl_xor_sync(0xffffffffu, ss, off);
    float sc = 1.0f / fmaxf(sqrtf(ss), 1e-12f);

    __nv_bfloat162* drow = (__nv_bfloat162*)(dst + (size_t)row * DIM);
    drow[lane * 2 + 0]      = __floats2bfloat162_rn(v0.x * sc, v0.y * sc);
    drow[lane * 2 + 1]      = __floats2bfloat162_rn(v0.z * sc, v0.w * sc);
    drow[64 + lane * 2 + 0] = __floats2bfloat162_rn(v1.x * sc, v1.y * sc);
    drow[64 + lane * 2 + 1] = __floats2bfloat162_rn(v1.z * sc, v1.w * sc);
}

// ---------------------------------------------------------------- fused attention
// out = (Vsum + sum_j (exp(s_j)-1) v_j) / (NK + sum_j (exp(s_j)-1)),  |s| <= SCALE.
// 8 warps: QK = 4 row-groups x 2 key-halves. Own-half P kept in registers
// (PV starts immediately); partner half exchanged through swizzled smem with
// a PAIRWISE named barrier. One CTA barrier per block (K/V buffer swap).
extern "C" __global__ void __launch_bounds__(THREADS, 1)
flash_kernel(float* __restrict__ out) {
    extern __shared__ __align__(128) char smem[];
    const uint32_t sb = smem_u32(smem);
    const int b  = blockIdx.y;
    const int q0 = blockIdx.x * BM;
    const int tid = threadIdx.x, lane = tid & 31, wid = tid >> 5;
    const int rg = wid >> 1;       // row group: rows rg*32 .. +31
    const int hf = wid & 1;        // QK: keys hf*32.. ; PV: cols hf*128..
    const int g = lane >> 3;
    const int xs = lane & 7;       // swizzle XOR

    float* sVS = (float*)(smem + SVS_OFF);
    float* sL  = (float*)(smem + SL_OFF);    // [2][128]

    // ---- load Q tile (swizzled) ----
    const uint4* gq = (const uint4*)(g_Qn + ((size_t)(b * NQ + q0)) * DIM);
    for (int i = tid; i < BM * 32; i += THREADS) {
        int r = i >> 5, c = i & 31;
        *(uint4*)(smem + SQ_OFF + r * 512 + ((c ^ (r & 7)) * 16)) = gq[i];
    }
    if (tid < DIM) sVS[tid] = g_Vsum[b * DIM + tid];

    const char* gK = (const char*)(g_Kn + (size_t)b * NK * DIM);
    const char* gV = (const char*)(g_Vb + (size_t)b * NK * DIM);

    // prefetch block 0
    for (int i = tid; i < 4096; i += THREADS) {
        int r = (i >> 5) & 63, c = i & 31;
        uint32_t dst = r * 512 + ((c ^ (r & 7)) * 16);
        if (i < 2048) cp16(sb + SK0_OFF + dst, gK + r * 512 + c * 16);
        else          cp16(sb + SV0_OFF + dst, gV + r * 512 + c * 16);
    }
    CP_COMMIT();

    // per-warp base addresses
    const uint32_t aQbase = sb + SQ_OFF + (uint32_t)((rg * 32 + (lane & 15)) * 512);
    const int qch = (lane >> 4);
    const uint32_t bKrow = (uint32_t)((hf * 32 + (g >> 1) * 8 + (lane & 7)) * 512);
    const int kch = (g & 1);
    const int prQuad = lane >> 2;
    const uint32_t aPbase = sb + SP_OFF + (uint32_t)((rg * 32 + (lane & 15)) * 128);
    const uint32_t bVrow = (uint32_t)(((g & 1) * 8 + (lane & 7)) * 512);

    float oAcc[32][4];
#pragma unroll
    for (int a = 0; a < 32; a++)
#pragma unroll
        for (int j = 0; j < 4; j++) oAcc[a][j] = 0.0f;

    float eL[2] = {0.0f, 0.0f}, eH[2] = {0.0f, 0.0f};

    for (int kb = 0; kb < NBLK; kb++) {
        const uint32_t skb = (kb & 1) ? SK1_OFF : SK0_OFF;
        const uint32_t svb = (kb & 1) ? SV1_OFF : SV0_OFF;

        CP_WAIT(0);        // buffer kb landed
        __syncthreads();   // all warps done with PV(kb-1) & P(kb-1)

        if (kb + 1 < NBLK) {
            const uint32_t skn = (kb & 1) ? SK0_OFF : SK1_OFF;
            const uint32_t svn = (kb & 1) ? SV0_OFF : SV1_OFF;
            const char* gKn = gK + (size_t)(kb + 1) * BN * 512;
            const char* gVn = gV + (size_t)(kb + 1) * BN * 512;
            for (int i = tid; i < 4096; i += THREADS) {
                int r = (i >> 5) & 63, c = i & 31;
                uint32_t dst = r * 512 + ((c ^ (r & 7)) * 16);
                if (i < 2048) cp16(sb + skn + dst, gKn + r * 512 + c * 16);
                else          cp16(sb + svn + dst, gVn + r * 512 + c * 16);
            }
            CP_COMMIT();
        }

        // ---- S = Q @ K^T : 32 rows x 32 keys per warp ----
        float sAcc[2][4][4];
#pragma unroll
        for (int m = 0; m < 2; m++)
#pragma unroll
            for (int a = 0; a < 4; a++)
#pragma unroll
                for (int j = 0; j < 4; j++) sAcc[m][a][j] = 0.0f;

#pragma unroll
        for (int ks = 0; ks < 16; ks++) {
            uint32_t qa0[4], qa1[4];
            const uint32_t qoff = (uint32_t)((((ks * 2 + qch) ^ xs)) * 16);
            LDSM_X4(qa0[0], qa0[1], qa0[2], qa0[3], aQbase + qoff);
            LDSM_X4(qa1[0], qa1[1], qa1[2], qa1[3], aQbase + 16 * 512 + qoff);
            const uint32_t koff = (uint32_t)((((ks * 2 + kch) ^ xs)) * 16);
#pragma unroll
            for (int kt = 0; kt < 2; kt++) {
                uint32_t b0, b1, b2, b3;
                LDSM_X4(b0, b1, b2, b3, sb + skb + bKrow + kt * (16 * 512) + koff);
                MMA16816(sAcc[0][kt * 2],     qa0[0], qa0[1], qa0[2], qa0[3], b0, b1);
                MMA16816(sAcc[0][kt * 2 + 1], qa0[0], qa0[1], qa0[2], qa0[3], b2, b3);
                MMA16816(sAcc[1][kt * 2],     qa1[0], qa1[1], qa1[2], qa1[3], b0, b1);
                MMA16816(sAcc[1][kt * 2 + 1], qa1[0], qa1[1], qa1[2], qa1[3], b2, b3);
            }
        }

        // ---- e = exp(s*SCALE)-1; row-sum partials; pack own-half A-frags; store P ----
        uint32_t pOwn[2][2][4];   // [m][kg][frag]; covers keys hf*32 + kg*16 .. +15
#pragma unroll
        for (int m = 0; m < 2; m++) {
#pragma unroll
            for (int a = 0; a < 4; a++) {
#pragma unroll
                for (int j = 0; j < 4; j++)
                    sAcc[m][a][j] = __expf(sAcc[m][a][j] * SCALE) - 1.0f;
                eL[m] += sAcc[m][a][0] + sAcc[m][a][1];
                eH[m] += sAcc[m][a][2] + sAcc[m][a][3];
            }
#pragma unroll
            for (int kg = 0; kg < 2; kg++) {
                __nv_bfloat162 t0 = __floats2bfloat162_rn(sAcc[m][2 * kg][0], sAcc[m][2 * kg][1]);
                __nv_bfloat162 t1 = __floats2bfloat162_rn(sAcc[m][2 * kg][2], sAcc[m][2 * kg][3]);
                __nv_bfloat162 t2 = __floats2bfloat162_rn(sAcc[m][2 * kg + 1][0], sAcc[m][2 * kg + 1][1]);
                __nv_bfloat162 t3 = __floats2bfloat162_rn(sAcc[m][2 * kg + 1][2], sAcc[m][2 * kg + 1][3]);
                pOwn[m][kg][0] = *(uint32_t*)&t0;
                pOwn[m][kg][1] = *(uint32_t*)&t1;
                pOwn[m][kg][2] = *(uint32_t*)&t2;
                pOwn[m][kg][3] = *(uint32_t*)&t3;
                // store own half to P smem for the partner (same values, C-layout)
                const uint32_t pr = (uint32_t)(rg * 32 + m * 16 + prQuad);
                const uint32_t addr0 = sb + SP_OFF + pr * 128 +
                    (uint32_t)((((hf * 4 + 2 * kg) ^ prQuad)) * 16) + (lane & 3) * 4;
                const uint32_t addr1 = sb + SP_OFF + pr * 128 +
                    (uint32_t)((((hf * 4 + 2 * kg + 1) ^ prQuad)) * 16) + (lane & 3) * 4;
                asm volatile("st.shared.b32 [%0], %1;" :: "r"(addr0), "r"(pOwn[m][kg][0]));
                asm volatile("st.shared.b32 [%0], %1;" :: "r"(addr0 + 8 * 128), "r"(pOwn[m][kg][1]));
                asm volatile("st.shared.b32 [%0], %1;" :: "r"(addr1), "r"(pOwn[m][kg][2]));
                asm volatile("st.shared.b32 [%0], %1;" :: "r"(addr1 + 8 * 128), "r"(pOwn[m][kg][3]));
            }
        }

        // ---- PV own half (P in registers) : keys hf*32 .. +31 ----
#pragma unroll
        for (int kg = 0; kg < 2; kg++) {
            const int kk = hf * 2 + kg;
            const uint32_t vrow = sb + svb + bVrow + (uint32_t)(kk * 16 * 512);
#pragma unroll
            for (int cg = 0; cg < 8; cg++) {
                uint32_t v0, v1, v2, v3;
                const int cc = hf * 16 + cg * 2 + (g >> 1);
                LDSM_X4_T(v0, v1, v2, v3, vrow + (uint32_t)(((cc ^ xs)) * 16));
                MMA16816(oAcc[cg * 2],          pOwn[0][kg][0], pOwn[0][kg][1], pOwn[0][kg][2], pOwn[0][kg][3], v0, v1);
                MMA16816(oAcc[cg * 2 + 1],      pOwn[0][kg][0], pOwn[0][kg][1], pOwn[0][kg][2], pOwn[0][kg][3], v2, v3);
                MMA16816(oAcc[16 + cg * 2],     pOwn[1][kg][0], pOwn[1][kg][1], pOwn[1][kg][2], pOwn[1][kg][3], v0, v1);
                MMA16816(oAcc[16 + cg * 2 + 1], pOwn[1][kg][0], pOwn[1][kg][1], pOwn[1][kg][2], pOwn[1][kg][3], v2, v3);
            }
        }

        BAR_SYNC(rg + 1, 64);   // pairwise: partner's P half visible

        // ---- PV partner half (P from smem) : keys (1-hf)*32 .. +31 ----
#pragma unroll
        for (int kg = 0; kg < 2; kg++) {
            const int kk = (1 - hf) * 2 + kg;
            uint32_t pa0[4], pa1[4];
            const uint32_t poff = (uint32_t)((((kk * 2 + qch) ^ xs)) * 16);
            LDSM_X4(pa0[0], pa0[1], pa0[2], pa0[3], aPbase + poff);
            LDSM_X4(pa1[0], pa1[1], pa1[2], pa1[3], aPbase + 16 * 128 + poff);
            const uint32_t vrow = sb + svb + bVrow + (uint32_t)(kk * 16 * 512);
#pragma unroll
            for (int cg = 0; cg < 8; cg++) {
                uint32_t v0, v1, v2, v3;
                const int cc = hf * 16 + cg * 2 + (g >> 1);
                LDSM_X4_T(v0, v1, v2, v3, vrow + (uint32_t)(((cc ^ xs)) * 16));
                MMA16816(oAcc[cg * 2],          pa0[0], pa0[1], pa0[2], pa0[3], v0, v1);
                MMA16816(oAcc[cg * 2 + 1],      pa0[0], pa0[1], pa0[2], pa0[3], v2, v3);
                MMA16816(oAcc[16 + cg * 2],     pa1[0], pa1[1], pa1[2], pa1[3], v0, v1);
                MMA16816(oAcc[16 + cg * 2 + 1], pa1[0], pa1[1], pa1[2], pa1[3], v2, v3);
            }
        }
    }

    // ---- finalize row sums ----
#pragma unroll
    for (int m = 0; m < 2; m++) {
        eL[m] += __shfl_xor_sync(0xffffffffu, eL[m], 1);
        eL[m] += __shfl_xor_sync(0xffffffffu, eL[m], 2);
        eH[m] += __shfl_xor_sync(0xffffffffu, eH[m], 1);
        eH[m] += __shfl_xor_sync(0xffffffffu, eH[m], 2);
    }
    if ((lane & 3) == 0) {
        const int r0 = rg * 32 + (lane >> 2);
        sL[hf * 128 + r0]      = eL[0];
        sL[hf * 128 + r0 + 8]  = eH[0];
        sL[hf * 128 + r0 + 16] = eL[1];
        sL[hf * 128 + r0 + 24] = eH[1];
    }
    __syncthreads();

    // ---- writeout: rows rg*32 + m*16 + quad (+8), cols hf*128 .. +127 ----
    float* opb = out + ((size_t)(b * NQ + q0)) * DIM;
#pragma unroll
    for (int m = 0; m < 2; m++) {
        const int r1 = rg * 32 + m * 16 + (lane >> 2);
        const float inv1 = 1.0f / ((float)NK + sL[r1] + sL[128 + r1]);
        const float inv2 = 1.0f / ((float)NK + sL[r1 + 8] + sL[128 + r1 + 8]);
        float* op = opb + (size_t)r1 * DIM;
#pragma unroll
        for (int cg = 0; cg < 16; cg++) {
            const int c = hf * 128 + cg * 8 + 2 * (lane & 3);
            float vs0 = sVS[c], vs1 = sVS[c + 1];
            float* acc = oAcc[m * 16 + cg];
            *(float2*)(op + c) =
                make_float2((vs0 + acc[0]) * inv1, (vs1 + acc[1]) * inv1);
            *(float2*)(op + 8 * DIM + c) =
                make_float2((vs0 + acc[2]) * inv2, (vs1 + acc[3]) * inv2);
        }
    }
}

// ---------------------------------------------------------------- launch
extern "C" void kernel_launch(void* const* d_in, const int* in_sizes, int n_in,
                              void* d_out, int out_size) {
    const float* q = (const float*)d_in[0];
    const float* k = (const float*)d_in[1];
    const float* v = (const float*)d_in[2];
    float* out = (float*)d_out;

    cudaFuncSetAttribute(flash_kernel, cudaFuncAttributeMaxDynamicSharedMemorySize, SMEM_BYTES);

    zero_vsum_kernel<<<1, BATCH * DIM>>>();
    vprep_kernel<<<dim3(NK / 128, BATCH), 256>>>(v);
    normalize_kernel<<<(2 * BATCH * NQ) / 8, 256>>>(q, k);
    flash_kernel<<<dim3(NQ / BM, BATCH), THREADS, SMEM_BYTES>>>(out);
}

// round 14
// speedup vs baseline: 1.0276x; 1.0276x over previous
#include <cuda_runtime.h>
#include <cuda_bf16.h>
#include <cstdint>

#define BATCH 4
#define NQ    4096
#define NK    4096
#define DIM   256
#define SCALE 0.17677669529663687f   // (256/8)^-0.5

#define BM 64
#define BN 64
#define NBLK (NK / BN)
#define THREADS 128

// device-global scratch (no allocations allowed)
__device__ __nv_bfloat16 g_Qn[BATCH * NQ * DIM];
__device__ __nv_bfloat16 g_Kn[BATCH * NK * DIM];
__device__ __nv_bfloat16 g_Vb[BATCH * NK * DIM];
__device__ float         g_Vsum[BATCH * DIM];

// smem layout (bytes) — XOR-swizzled tiles, 512B rows; SINGLE K/V buffer
#define SQ_OFF  0u            // Q 64 x 256 bf16 = 32768
#define SK_OFF  32768u        // K 64 x 256 bf16 = 32768
#define SV_OFF  65536u        // V 64 x 256 bf16 = 32768
#define SP_OFF  98304u        // P 64 x 64 bf16 = 8192 (128B rows, swizzled)
#define SVS_OFF 106496u       // float[256]
#define SL_OFF  107520u       // float[2][64]
static const int SMEM_BYTES = 108032;

// ---------------------------------------------------------------- helpers
__device__ __forceinline__ uint32_t smem_u32(const void* p) {
    return (uint32_t)__cvta_generic_to_shared(p);
}

#define LDSM_X4(r0, r1, r2, r3, addr)                                              \
    asm volatile("ldmatrix.sync.aligned.m8n8.x4.shared.b16 {%0,%1,%2,%3},[%4];"    \
                 : "=r"(r0), "=r"(r1), "=r"(r2), "=r"(r3) : "r"(addr))

#define LDSM_X4_T(r0, r1, r2, r3, addr)                                                 \
    asm volatile("ldmatrix.sync.aligned.m8n8.x4.trans.shared.b16 {%0,%1,%2,%3},[%4];"   \
                 : "=r"(r0), "=r"(r1), "=r"(r2), "=r"(r3) : "r"(addr))

#define MMA16816(d, a0, a1, a2, a3, b0, b1)                                        \
    asm volatile("mma.sync.aligned.m16n8k16.row.col.f32.bf16.bf16.f32 "            \
                 "{%0,%1,%2,%3},{%4,%5,%6,%7},{%8,%9},{%0,%1,%2,%3};"              \
                 : "+f"(d[0]), "+f"(d[1]), "+f"(d[2]), "+f"(d[3])                  \
                 : "r"(a0), "r"(a1), "r"(a2), "r"(a3), "r"(b0), "r"(b1))

__device__ __forceinline__ void cp16(uint32_t s, const void* g) {
    asm volatile("cp.async.cg.shared.global [%0], [%1], 16;" :: "r"(s), "l"(g));
}
#define CP_COMMIT() asm volatile("cp.async.commit_group;" ::: "memory")
#define CP_WAIT(n)  asm volatile("cp.async.wait_group %0;" :: "n"(n) : "memory")
#define BAR_SYNC(id, cnt) asm volatile("bar.sync %0, %1;" :: "r"(id), "r"(cnt) : "memory")

// ---------------------------------------------------------------- prep kernels
__global__ void zero_vsum_kernel() { g_Vsum[threadIdx.x] = 0.0f; }

__global__ void vprep_kernel(const float* __restrict__ v) {
    int b = blockIdx.y, chunk = blockIdx.x, d = threadIdx.x;
    size_t base = ((size_t)b * NK + (size_t)chunk * 128) * DIM + d;
    float sum = 0.0f;
    for (int r = 0; r < 128; r++) {
        float x = v[base + (size_t)r * DIM];
        sum += x;
        g_Vb[base + (size_t)r * DIM] = __float2bfloat16(x);
    }
    atomicAdd(&g_Vsum[b * DIM + d], sum);
}

__global__ void normalize_kernel(const float* __restrict__ q, const float* __restrict__ k) {
    int gw = (blockIdx.x * blockDim.x + threadIdx.x) >> 5;
    int lane = threadIdx.x & 31;
    const float* src;
    __nv_bfloat16* dst;
    int row;
    if (gw < BATCH * NQ) { src = q; dst = g_Qn; row = gw; }
    else                 { src = k; dst = g_Kn; row = gw - BATCH * NQ; }

    const float4* p = (const float4*)(src + (size_t)row * DIM);
    float4 v0 = p[lane];
    float4 v1 = p[lane + 32];
    float ss = v0.x * v0.x + v0.y * v0.y + v0.z * v0.z + v0.w * v0.w
             + v1.x * v1.x + v1.y * v1.y + v1.z * v1.z + v1.w * v1.w;
#pragma unroll
    for (int off = 16; off > 0; off >>= 1) ss += __shfl_xor_sync(0xffffffffu, ss, off);
    float sc = 1.0f / fmaxf(sqrtf(ss), 1e-12f);

    __nv_bfloat162* drow = (__nv_bfloat162*)(dst + (size_t)row * DIM);
    drow[lane * 2 + 0]      = __floats2bfloat162_rn(v0.x * sc, v0.y * sc);
    drow[lane * 2 + 1]      = __floats2bfloat162_rn(v0.z * sc, v0.w * sc);
    drow[64 + lane * 2 + 0] = __floats2bfloat162_rn(v1.x * sc, v1.y * sc);
    drow[64 + lane * 2 + 1] = __floats2bfloat162_rn(v1.z * sc, v1.w * sc);
}

// ---------------------------------------------------------------- fused attention
// out = (Vsum + sum_j (exp(s_j)-1) v_j) / (NK + sum_j (exp(s_j)-1)),  |s| <= SCALE.
// BM=64, 4 warps, 2 CTAs/SM: warp tiles identical to the proven BM=128 kernel
// (QK 32rows x 32keys, PV 32rows x 128cols). Single-buffered K/V — the load
// exposure is hidden by the co-resident CTA, whose barriers are independent.
extern "C" __global__ void __launch_bounds__(THREADS, 2)
flash_kernel(float* __restrict__ out) {
    extern __shared__ __align__(128) char smem[];
    const uint32_t sb = smem_u32(smem);
    const int b  = blockIdx.y;
    const int q0 = blockIdx.x * BM;
    const int tid = threadIdx.x, lane = tid & 31, wid = tid >> 5;
    const int rg = wid >> 1;       // row group: rows rg*32 .. +31  (0..1)
    const int hf = wid & 1;        // QK: keys hf*32.. ; PV: cols hf*128..
    const int g = lane >> 3;
    const int xs = lane & 7;       // swizzle XOR

    float* sVS = (float*)(smem + SVS_OFF);
    float* sL  = (float*)(smem + SL_OFF);    // [2][64]

    // ---- load Q tile (swizzled) ----
    const uint4* gq = (const uint4*)(g_Qn + ((size_t)(b * NQ + q0)) * DIM);
    for (int i = tid; i < BM * 32; i += THREADS) {
        int r = i >> 5, c = i & 31;
        *(uint4*)(smem + SQ_OFF + r * 512 + ((c ^ (r & 7)) * 16)) = gq[i];
    }
    for (int i = tid; i < DIM; i += THREADS) sVS[i] = g_Vsum[b * DIM + i];

    const char* gK = (const char*)(g_Kn + (size_t)b * NK * DIM);
    const char* gV = (const char*)(g_Vb + (size_t)b * NK * DIM);

    // per-warp base addresses (identical math to the BM=128 kernel)
    const uint32_t aQbase = sb + SQ_OFF + (uint32_t)((rg * 32 + (lane & 15)) * 512);
    const int qch = (lane >> 4);
    const uint32_t bKrow = (uint32_t)((hf * 32 + (g >> 1) * 8 + (lane & 7)) * 512);
    const int kch = (g & 1);
    const int prQuad = lane >> 2;
    const uint32_t aPbase = sb + SP_OFF + (uint32_t)((rg * 32 + (lane & 15)) * 128);
    const uint32_t bVrow = (uint32_t)(((g & 1) * 8 + (lane & 7)) * 512);

    float oAcc[32][4];
#pragma unroll
    for (int a = 0; a < 32; a++)
#pragma unroll
        for (int j = 0; j < 4; j++) oAcc[a][j] = 0.0f;

    float eL[2] = {0.0f, 0.0f}, eH[2] = {0.0f, 0.0f};

    for (int kb = 0; kb < NBLK; kb++) {
        __syncthreads();   // all reads of K/V/P(kb-1) done (kb=0: Q stores ordered)

        // ---- load K,V(kb) into the single buffer ----
        const char* gKb = gK + (size_t)kb * BN * 512;
        const char* gVb2 = gV + (size_t)kb * BN * 512;
        for (int i = tid; i < 4096; i += THREADS) {
            int r = (i >> 5) & 63, c = i & 31;
            uint32_t dst = r * 512 + ((c ^ (r & 7)) * 16);
            if (i < 2048) cp16(sb + SK_OFF + dst, gKb + r * 512 + c * 16);
            else          cp16(sb + SV_OFF + dst, gVb2 + r * 512 + c * 16);
        }
        CP_COMMIT();
        CP_WAIT(0);
        __syncthreads();   // tile visible to all warps

        // ---- S = Q @ K^T : 32 rows x 32 keys per warp ----
        float sAcc[2][4][4];
#pragma unroll
        for (int m = 0; m < 2; m++)
#pragma unroll
            for (int a = 0; a < 4; a++)
#pragma unroll
                for (int j = 0; j < 4; j++) sAcc[m][a][j] = 0.0f;

#pragma unroll
        for (int ks = 0; ks < 16; ks++) {
            uint32_t qa0[4], qa1[4];
            const uint32_t qoff = (uint32_t)((((ks * 2 + qch) ^ xs)) * 16);
            LDSM_X4(qa0[0], qa0[1], qa0[2], qa0[3], aQbase + qoff);
            LDSM_X4(qa1[0], qa1[1], qa1[2], qa1[3], aQbase + 16 * 512 + qoff);
            const uint32_t koff = (uint32_t)((((ks * 2 + kch) ^ xs)) * 16);
#pragma unroll
            for (int kt = 0; kt < 2; kt++) {
                uint32_t b0, b1, b2, b3;
                LDSM_X4(b0, b1, b2, b3, sb + SK_OFF + bKrow + kt * (16 * 512) + koff);
                MMA16816(sAcc[0][kt * 2],     qa0[0], qa0[1], qa0[2], qa0[3], b0, b1);
                MMA16816(sAcc[0][kt * 2 + 1], qa0[0], qa0[1], qa0[2], qa0[3], b2, b3);
                MMA16816(sAcc[1][kt * 2],     qa1[0], qa1[1], qa1[2], qa1[3], b0, b1);
                MMA16816(sAcc[1][kt * 2 + 1], qa1[0], qa1[1], qa1[2], qa1[3], b2, b3);
            }
        }

        // ---- e = exp(s*SCALE)-1; row-sum partials; P -> smem (swizzled) ----
#pragma unroll
        for (int m = 0; m < 2; m++) {
#pragma unroll
            for (int a = 0; a < 4; a++) {
#pragma unroll
                for (int j = 0; j < 4; j++)
                    sAcc[m][a][j] = __expf(sAcc[m][a][j] * SCALE) - 1.0f;
                eL[m] += sAcc[m][a][0] + sAcc[m][a][1];
                eH[m] += sAcc[m][a][2] + sAcc[m][a][3];
            }
#pragma unroll
            for (int a = 0; a < 4; a++) {
                const uint32_t pr = (uint32_t)(rg * 32 + m * 16 + prQuad);
                const uint32_t addr = sb + SP_OFF + pr * 128 +
                    (uint32_t)((((hf * 4 + a) ^ prQuad)) * 16) + (lane & 3) * 4;
                __nv_bfloat162 t0 = __floats2bfloat162_rn(sAcc[m][a][0], sAcc[m][a][1]);
                __nv_bfloat162 t1 = __floats2bfloat162_rn(sAcc[m][a][2], sAcc[m][a][3]);
                asm volatile("st.shared.b32 [%0], %1;" :: "r"(addr), "r"(*(uint32_t*)&t0));
                asm volatile("st.shared.b32 [%0], %1;" :: "r"(addr + 8 * 128), "r"(*(uint32_t*)&t1));
            }
        }
        BAR_SYNC(rg + 1, 64);   // pair barrier: both key-halves of P visible

        // ---- O += P @ V : 32 rows x 128 cols per warp, 64 keys ----
#pragma unroll
        for (int kk = 0; kk < 4; kk++) {
            uint32_t pa0[4], pa1[4];
            const uint32_t poff = (uint32_t)((((kk * 2 + qch) ^ xs)) * 16);
            LDSM_X4(pa0[0], pa0[1], pa0[2], pa0[3], aPbase + poff);
            LDSM_X4(pa1[0], pa1[1], pa1[2], pa1[3], aPbase + 16 * 128 + poff);
            const uint32_t vrow = sb + SV_OFF + bVrow + (uint32_t)(kk * 16 * 512);
#pragma unroll
            for (int cg = 0; cg < 8; cg++) {
                uint32_t v0, v1, v2, v3;
                const int cc = hf * 16 + cg * 2 + (g >> 1);
                LDSM_X4_T(v0, v1, v2, v3, vrow + (uint32_t)(((cc ^ xs)) * 16));
                MMA16816(oAcc[cg * 2],          pa0[0], pa0[1], pa0[2], pa0[3], v0, v1);
                MMA16816(oAcc[cg * 2 + 1],      pa0[0], pa0[1], pa0[2], pa0[3], v2, v3);
                MMA16816(oAcc[16 + cg * 2],     pa1[0], pa1[1], pa1[2], pa1[3], v0, v1);
                MMA16816(oAcc[16 + cg * 2 + 1], pa1[0], pa1[1], pa1[2], pa1[3], v2, v3);
            }
        }
    }

    // ---- finalize row sums ----
#pragma unroll
    for (int m = 0; m < 2; m++) {
        eL[m] += __shfl_xor_sync(0xffffffffu, eL[m], 1);
        eL[m] += __shfl_xor_sync(0xffffffffu, eL[m], 2);
        eH[m] += __shfl_xor_sync(0xffffffffu, eH[m], 1);
        eH[m] += __shfl_xor_sync(0xffffffffu, eH[m], 2);
    }
    if ((lane & 3) == 0) {
        const int r0 = rg * 32 + (lane >> 2);
        sL[hf * 64 + r0]      = eL[0];
        sL[hf * 64 + r0 + 8]  = eH[0];
        sL[hf * 64 + r0 + 16] = eL[1];
        sL[hf * 64 + r0 + 24] = eH[1];
    }
    __syncthreads();

    // ---- writeout: rows rg*32 + m*16 + quad (+8), cols hf*128 .. +127 ----
    float* opb = out + ((size_t)(b * NQ + q0)) * DIM;
#pragma unroll
    for (int m = 0; m < 2; m++) {
        const int r1 = rg * 32 + m * 16 + (lane >> 2);
        const float inv1 = 1.0f / ((float)NK + sL[r1] + sL[64 + r1]);
        const float inv2 = 1.0f / ((float)NK + sL[r1 + 8] + sL[64 + r1 + 8]);
        float* op = opb + (size_t)r1 * DIM;
#pragma unroll
        for (int cg = 0; cg < 16; cg++) {
            const int c = hf * 128 + cg * 8 + 2 * (lane & 3);
            float vs0 = sVS[c], vs1 = sVS[c + 1];
            float* acc = oAcc[m * 16 + cg];
            *(float2*)(op + c) =
                make_float2((vs0 + acc[0]) * inv1, (vs1 + acc[1]) * inv1);
            *(float2*)(op + 8 * DIM + c) =
                make_float2((vs0 + acc[2]) * inv2, (vs1 + acc[3]) * inv2);
        }
    }
}

// ---------------------------------------------------------------- launch
extern "C" void kernel_launch(void* const* d_in, const int* in_sizes, int n_in,
                              void* d_out, int out_size) {
    const float* q = (const float*)d_in[0];
    const float* k = (const float*)d_in[1];
    const float* v = (const float*)d_in[2];
    float* out = (float*)d_out;

    cudaFuncSetAttribute(flash_kernel, cudaFuncAttributeMaxDynamicSharedMemorySize, SMEM_BYTES);

    zero_vsum_kernel<<<1, BATCH * DIM>>>();
    vprep_kernel<<<dim3(NK / 128, BATCH), 256>>>(v);
    normalize_kernel<<<(2 * BATCH * NQ) / 8, 256>>>(q, k);
    flash_kernel<<<dim3(NQ / BM, BATCH), THREADS, SMEM_BYTES>>>(out);
}

// round 15
// speedup vs baseline: 3.2846x; 3.1964x over previous
#include <cuda_runtime.h>
#include <cuda_bf16.h>
#include <cstdint>

#define BATCH 4
#define NQ    4096
#define NK    4096
#define DIM   256
#define SCALE 0.17677669529663687f   // (256/8)^-0.5

// device-global scratch (no allocations allowed)
__device__ __nv_bfloat16 g_Qb[BATCH * NQ * DIM];   // SCALE * normalized Q, [b][q][d]
__device__ __nv_bfloat16 g_KT[BATCH * DIM * NK];   // normalized K transposed, [b][d][j]
__device__ __nv_bfloat16 g_VT[BATCH * DIM * NK];   // V bf16 transposed, [b][d][j]
__device__ float         g_C [BATCH * DIM * DIM];  // G[dv][dk] = sum_j V[j][dv] K[j][dk]
__device__ __nv_bfloat16 g_Cb[BATCH * DIM * DIM];  // bf16 copy of g_C
__device__ float         g_Ksum[BATCH * DIM];      // sum_j kn[j][d]
__device__ float         g_Vsum[BATCH * DIM];      // sum_j v[j][d]

// ---------------------------------------------------------------- helpers
__device__ __forceinline__ uint32_t smem_u32(const void* p) {
    return (uint32_t)__cvta_generic_to_shared(p);
}

#define LDSM_X4(r0, r1, r2, r3, addr)                                              \
    asm volatile("ldmatrix.sync.aligned.m8n8.x4.shared.b16 {%0,%1,%2,%3},[%4];"    \
                 : "=r"(r0), "=r"(r1), "=r"(r2), "=r"(r3) : "r"(addr))

#define MMA16816(d, a0, a1, a2, a3, b0, b1)                                        \
    asm volatile("mma.sync.aligned.m16n8k16.row.col.f32.bf16.bf16.f32 "            \
                 "{%0,%1,%2,%3},{%4,%5,%6,%7},{%8,%9},{%0,%1,%2,%3};"              \
                 : "+f"(d[0]), "+f"(d[1]), "+f"(d[2]), "+f"(d[3])                  \
                 : "r"(a0), "r"(a1), "r"(a2), "r"(a3), "r"(b0), "r"(b1))

__device__ __forceinline__ void cp16(uint32_t s, const void* g) {
    asm volatile("cp.async.cg.shared.global [%0], [%1], 16;" :: "r"(s), "l"(g));
}
#define CP_COMMIT() asm volatile("cp.async.commit_group;" ::: "memory")
#define CP_WAIT(n)  asm volatile("cp.async.wait_group %0;" :: "n"(n) : "memory")

// ---------------------------------------------------------------- init
__global__ void zero_kernel() {
    int i = blockIdx.x * 256 + threadIdx.x;           // grid 1032*256 = 264192
    if (i < BATCH * DIM * DIM) g_C[i] = 0.0f;
    else if (i < BATCH * DIM * DIM + BATCH * DIM) g_Ksum[i - BATCH * DIM * DIM] = 0.0f;
    else g_Vsum[i - BATCH * DIM * DIM - BATCH * DIM] = 0.0f;
}

// ---------------------------------------------------------------- Q normalize (x SCALE)
__global__ void qnorm_kernel(const float* __restrict__ q) {
    int row = (blockIdx.x * blockDim.x + threadIdx.x) >> 5;   // 0..16383
    int lane = threadIdx.x & 31;
    const float4* p = (const float4*)(q + (size_t)row * DIM);
    float4 v0 = p[lane];
    float4 v1 = p[lane + 32];
    float ss = v0.x * v0.x + v0.y * v0.y + v0.z * v0.z + v0.w * v0.w
             + v1.x * v1.x + v1.y * v1.y + v1.z * v1.z + v1.w * v1.w;
#pragma unroll
    for (int off = 16; off > 0; off >>= 1) ss += __shfl_xor_sync(0xffffffffu, ss, off);
    float sc = SCALE / fmaxf(sqrtf(ss), 1e-12f);
    __nv_bfloat162* drow = (__nv_bfloat162*)(g_Qb + (size_t)row * DIM);
    drow[lane * 2 + 0]      = __floats2bfloat162_rn(v0.x * sc, v0.y * sc);
    drow[lane * 2 + 1]      = __floats2bfloat162_rn(v0.z * sc, v0.w * sc);
    drow[64 + lane * 2 + 0] = __floats2bfloat162_rn(v1.x * sc, v1.y * sc);
    drow[64 + lane * 2 + 1] = __floats2bfloat162_rn(v1.z * sc, v1.w * sc);
}

// ---------------------------------------------------------------- K normalize + transpose + Ksum
__global__ void ktrans_kernel(const float* __restrict__ k) {
    __shared__ __nv_bfloat16 sT[DIM][72];   // [d][j_local], 144B rows (16B-mult)
    int b = blockIdx.y, j0 = blockIdx.x * 64;
    int tid = threadIdx.x, lane = tid & 31, wid = tid >> 5;
    // phase A: each warp normalizes 8 rows
    for (int rr = 0; rr < 8; rr++) {
        int jl = wid * 8 + rr;
        const float4* p = (const float4*)(k + ((size_t)(b * NK + j0 + jl)) * DIM);
        float4 v0 = p[lane];
        float4 v1 = p[lane + 32];
        float ss = v0.x * v0.x + v0.y * v0.y + v0.z * v0.z + v0.w * v0.w
                 + v1.x * v1.x + v1.y * v1.y + v1.z * v1.z + v1.w * v1.w;
#pragma unroll
        for (int off = 16; off > 0; off >>= 1) ss += __shfl_xor_sync(0xffffffffu, ss, off);
        float sc = 1.0f / fmaxf(sqrtf(ss), 1e-12f);
        sT[lane * 4 + 0][jl] = __float2bfloat16(v0.x * sc);
        sT[lane * 4 + 1][jl] = __float2bfloat16(v0.y * sc);
        sT[lane * 4 + 2][jl] = __float2bfloat16(v0.z * sc);
        sT[lane * 4 + 3][jl] = __float2bfloat16(v0.w * sc);
        sT[128 + lane * 4 + 0][jl] = __float2bfloat16(v1.x * sc);
        sT[128 + lane * 4 + 1][jl] = __float2bfloat16(v1.y * sc);
        sT[128 + lane * 4 + 2][jl] = __float2bfloat16(v1.z * sc);
        sT[128 + lane * 4 + 3][jl] = __float2bfloat16(v1.w * sc);
    }
    __syncthreads();
    // phase B: ksum partial + transposed write
    {
        float s = 0.0f;
#pragma unroll 8
        for (int j = 0; j < 64; j++) s += __bfloat162float(sT[tid][j]);
        atomicAdd(&g_Ksum[b * DIM + tid], s);
        uint4* dst = (uint4*)(g_KT + ((size_t)(b * DIM + tid)) * NK + j0);
        const uint4* src = (const uint4*)(&sT[tid][0]);
#pragma unroll
        for (int c = 0; c < 8; c++) dst[c] = src[c];
    }
}

// ---------------------------------------------------------------- V transpose + Vsum (from R3)
__global__ void vtrans_kernel(const float* __restrict__ v) {
    __shared__ __nv_bfloat16 sT[DIM][72];
    int b = blockIdx.y, k0 = blockIdx.x * 64;
    int tid = threadIdx.x;
    int c4 = tid & 63;
    int r0 = tid >> 6;
    const float4* gv = (const float4*)(v + ((size_t)(b * NK + k0)) * DIM);
    float s0 = 0, s1 = 0, s2 = 0, s3 = 0;
#pragma unroll
    for (int j = 0; j < 16; j++) {
        int r = r0 + j * 4;
        float4 x = gv[r * 64 + c4];
        s0 += x.x; s1 += x.y; s2 += x.z; s3 += x.w;
        sT[c4 * 4 + 0][r] = __float2bfloat16(x.x);
        sT[c4 * 4 + 1][r] = __float2bfloat16(x.y);
        sT[c4 * 4 + 2][r] = __float2bfloat16(x.z);
        sT[c4 * 4 + 3][r] = __float2bfloat16(x.w);
    }
    atomicAdd(&g_Vsum[b * DIM + c4 * 4 + 0], s0);
    atomicAdd(&g_Vsum[b * DIM + c4 * 4 + 1], s1);
    atomicAdd(&g_Vsum[b * DIM + c4 * 4 + 2], s2);
    atomicAdd(&g_Vsum[b * DIM + c4 * 4 + 3], s3);
    __syncthreads();
    for (int i = tid; i < 2048; i += 256) {
        int d = i >> 3, ch = i & 7;
        *(uint4*)(g_VT + ((size_t)(b * DIM + d)) * NK + k0 + ch * 8) =
            *(const uint4*)(&sT[d][ch * 8]);
    }
}

// ---------------------------------------------------------------- GEMM1: G[dv][dk] += VT * KT^T (over key slab)
// grid (16 ksplit, 2 mhalf, 4 batch), 256 thr, smem 192KB
extern "C" __global__ void __launch_bounds__(256, 1)
gemm1_kernel() {
    extern __shared__ __align__(128) char smem[];
    const uint32_t sb = smem_u32(smem);
    const int ksp = blockIdx.x, mh = blockIdx.y, b = blockIdx.z;
    const int j0 = ksp * 256;
    const int tid = threadIdx.x, lane = tid & 31, wid = tid >> 5;
    const int m0 = (wid >> 2) * 64, n0 = (wid & 3) * 64;
    const int g = lane >> 3, xs = lane & 7;

    const char* srcA = (const char*)g_VT + (size_t)((b * DIM + mh * 128) * (size_t)NK + j0) * 2;
    const char* srcB = (const char*)g_KT + (size_t)((b * DIM) * (size_t)NK + j0) * 2;
    for (int i = tid; i < 4096; i += 256) {
        int r = i >> 5, c = i & 31;
        cp16(sb + r * 512 + ((c ^ (r & 7)) * 16), srcA + (size_t)r * (NK * 2) + c * 16);
    }
    for (int i = tid; i < 8192; i += 256) {
        int r = i >> 5, c = i & 31;
        cp16(sb + 65536u + r * 512 + ((c ^ (r & 7)) * 16), srcB + (size_t)r * (NK * 2) + c * 16);
    }
    CP_COMMIT(); CP_WAIT(0); __syncthreads();

    float acc[32][4];
#pragma unroll
    for (int a = 0; a < 32; a++)
#pragma unroll
        for (int j = 0; j < 4; j++) acc[a][j] = 0.0f;

    const uint32_t aBase = sb + (uint32_t)((m0 + (lane & 15)) * 512);
    const uint32_t bBase = sb + 65536u + (uint32_t)((n0 + (g >> 1) * 8 + (lane & 7)) * 512);
    const int ach = lane >> 4, bch = g & 1;

#pragma unroll
    for (int ks = 0; ks < 16; ks++) {
        uint32_t A[4][4];
        const uint32_t aoff = (uint32_t)(((ks * 2 + ach) ^ xs) * 16);
#pragma unroll
        for (int mt = 0; mt < 4; mt++)
            LDSM_X4(A[mt][0], A[mt][1], A[mt][2], A[mt][3], aBase + mt * 16 * 512 + aoff);
        const uint32_t boff = (uint32_t)(((ks * 2 + bch) ^ xs) * 16);
#pragma unroll
        for (int nt = 0; nt < 4; nt++) {
            uint32_t b0, b1, b2, b3;
            LDSM_X4(b0, b1, b2, b3, bBase + nt * 16 * 512 + boff);
#pragma unroll
            for (int mt = 0; mt < 4; mt++) {
                MMA16816(acc[mt * 8 + nt * 2],     A[mt][0], A[mt][1], A[mt][2], A[mt][3], b0, b1);
                MMA16816(acc[mt * 8 + nt * 2 + 1], A[mt][0], A[mt][1], A[mt][2], A[mt][3], b2, b3);
            }
        }
    }

    float* Cb = g_C + (size_t)(b * DIM + mh * 128) * DIM;
#pragma unroll
    for (int mt = 0; mt < 4; mt++) {
#pragma unroll
        for (int nt = 0; nt < 4; nt++) {
#pragma unroll
            for (int h = 0; h < 2; h++) {
                float* a4 = acc[mt * 8 + nt * 2 + h];
                int row = m0 + mt * 16 + (lane >> 2);
                int col = n0 + nt * 16 + h * 8 + (lane & 3) * 2;
                atomicAdd(&Cb[(size_t)row * DIM + col],     a4[0]);
                atomicAdd(&Cb[(size_t)row * DIM + col + 1], a4[1]);
                atomicAdd(&Cb[(size_t)(row + 8) * DIM + col],     a4[2]);
                atomicAdd(&Cb[(size_t)(row + 8) * DIM + col + 1], a4[3]);
            }
        }
    }
}

// ---------------------------------------------------------------- convert C -> bf16
__global__ void convc_kernel() {
    int i = blockIdx.x * 256 + threadIdx.x;   // grid 1024*256
    g_Cb[i] = __float2bfloat16(g_C[i]);
}

// ---------------------------------------------------------------- GEMM2 + epilogue
// W[q][dv] = sum_dk Qb[q][dk] * G[dv][dk];  out = (Vsum[dv] + W) / (NK + Qb[q].Ksum)
// grid (32 qtile, 4 batch), 256 thr, smem ~200KB
#define G2_SQ   0u
#define G2_SG   65536u
#define G2_SVS  196608u
#define G2_SKS  197632u
#define G2_SDP  198656u
#define G2_SDEN 199680u
static const int G2_SMEM = 200192;

extern "C" __global__ void __launch_bounds__(256, 1)
gemm2_kernel(float* __restrict__ out) {
    extern __shared__ __align__(128) char smem[];
    const uint32_t sb = smem_u32(smem);
    const int qt = blockIdx.x, b = blockIdx.y;
    const int q0 = qt * 128;
    const int tid = threadIdx.x, lane = tid & 31, wid = tid >> 5;
    const int rg = wid >> 1, ch = wid & 1;
    const int g = lane >> 3, xs = lane & 7;

    float* sVS  = (float*)(smem + G2_SVS);
    float* sKS  = (float*)(smem + G2_SKS);
    float* sDP  = (float*)(smem + G2_SDP);
    float* sDEN = (float*)(smem + G2_SDEN);

    const char* srcQ = (const char*)g_Qb + (size_t)(b * NQ + q0) * DIM * 2;
    const char* srcG = (const char*)g_Cb + (size_t)b * DIM * DIM * 2;
    for (int i = tid; i < 4096; i += 256) {
        int r = i >> 5, c = i & 31;
        cp16(sb + G2_SQ + r * 512 + ((c ^ (r & 7)) * 16), srcQ + i * 16);
    }
    for (int i = tid; i < 8192; i += 256) {
        int r = i >> 5, c = i & 31;
        cp16(sb + G2_SG + r * 512 + ((c ^ (r & 7)) * 16), srcG + i * 16);
    }
    if (tid < DIM) { sVS[tid] = g_Vsum[b * DIM + tid]; sKS[tid] = g_Ksum[b * DIM + tid]; }
    CP_COMMIT(); CP_WAIT(0);
    __syncthreads();

    // denominator partials: thread t handles row t>>1, dim half t&1 (reads swizzled sQ)
    {
        int r = tid >> 1, hh = tid & 1;
        int xr = r & 7;
        float s = 0.0f;
#pragma unroll 16
        for (int i = 0; i < 128; i++) {
            int d = hh * 128 + i;
            uint32_t addr = (uint32_t)(r * 512 + (((d >> 3) ^ xr) * 16) + (d & 7) * 2);
            __nv_bfloat16 qv = *(__nv_bfloat16*)(smem + G2_SQ + addr);
            s += __bfloat162float(qv) * sKS[d];
        }
        sDP[tid] = s;
    }
    __syncthreads();
    if (tid < 128) sDEN[tid] = 1.0f / ((float)NK + sDP[2 * tid] + sDP[2 * tid + 1]);
    __syncthreads();

    float acc[32][4];
#pragma unroll
    for (int a = 0; a < 32; a++)
#pragma unroll
        for (int j = 0; j < 4; j++) acc[a][j] = 0.0f;

    const uint32_t aBase = sb + G2_SQ + (uint32_t)((rg * 32 + (lane & 15)) * 512);
    const uint32_t bBase = sb + G2_SG + (uint32_t)((ch * 128 + (g >> 1) * 8 + (lane & 7)) * 512);
    const int ach = lane >> 4, bch = g & 1;

#pragma unroll
    for (int ks = 0; ks < 16; ks++) {
        uint32_t A[2][4];
        const uint32_t aoff = (uint32_t)(((ks * 2 + ach) ^ xs) * 16);
        LDSM_X4(A[0][0], A[0][1], A[0][2], A[0][3], aBase + aoff);
        LDSM_X4(A[1][0], A[1][1], A[1][2], A[1][3], aBase + 16 * 512 + aoff);
        const uint32_t boff = (uint32_t)(((ks * 2 + bch) ^ xs) * 16);
#pragma unroll
        for (int nt = 0; nt < 8; nt++) {
            uint32_t b0, b1, b2, b3;
            LDSM_X4(b0, b1, b2, b3, bBase + nt * 16 * 512 + boff);
#pragma unroll
            for (int mt = 0; mt < 2; mt++) {
                MMA16816(acc[mt * 16 + nt * 2],     A[mt][0], A[mt][1], A[mt][2], A[mt][3], b0, b1);
                MMA16816(acc[mt * 16 + nt * 2 + 1], A[mt][0], A[mt][1], A[mt][2], A[mt][3], b2, b3);
            }
        }
    }

    // epilogue: out = (Vsum + W) * inv(denom)
    float* opb = out + (size_t)(b * NQ + q0) * DIM;
#pragma unroll
    for (int mt = 0; mt < 2; mt++) {
        const int r1 = rg * 32 + mt * 16 + (lane >> 2);
        const float inv1 = sDEN[r1];
        const float inv2 = sDEN[r1 + 8];
        float* op = opb + (size_t)r1 * DIM;
#pragma unroll
        for (int j8 = 0; j8 < 16; j8++) {
            const int c = ch * 128 + j8 * 8 + 2 * (lane & 3);
            float vs0 = sVS[c], vs1 = sVS[c + 1];
            float* a4 = acc[mt * 16 + j8];
            *(float2*)(op + c) =
                make_float2((vs0 + a4[0]) * inv1, (vs1 + a4[1]) * inv1);
            *(float2*)(op + 8 * DIM + c) =
                make_float2((vs0 + a4[2]) * inv2, (vs1 + a4[3]) * inv2);
        }
    }
}

// ---------------------------------------------------------------- launch
extern "C" void kernel_launch(void* const* d_in, const int* in_sizes, int n_in,
                              void* d_out, int out_size) {
    const float* q = (const float*)d_in[0];
    const float* k = (const float*)d_in[1];
    const float* v = (const float*)d_in[2];
    float* out = (float*)d_out;

    cudaFuncSetAttribute(gemm1_kernel, cudaFuncAttributeMaxDynamicSharedMemorySize, 196608);
    cudaFuncSetAttribute(gemm2_kernel, cudaFuncAttributeMaxDynamicSharedMemorySize, G2_SMEM);

    zero_kernel<<<1032, 256>>>();
    qnorm_kernel<<<(BATCH * NQ) / 8, 256>>>(q);
    ktrans_kernel<<<dim3(NK / 64, BATCH), 256>>>(k);
    vtrans_kernel<<<dim3(NK / 64, BATCH), 256>>>(v);
    gemm1_kernel<<<dim3(16, 2, BATCH), 256, 196608>>>();
    convc_kernel<<<1024, 256>>>();
    gemm2_kernel<<<dim3(NQ / 128, BATCH), 256, G2_SMEM>>>(out);
}

// round 17
// speedup vs baseline: 4.1456x; 1.2621x over previous
#include <cuda_runtime.h>
#include <cuda_bf16.h>
#include <cstdint>

#define BATCH 4
#define NQ    4096
#define NK    4096
#define DIM   256
#define SCALE 0.17677669529663687f   // (256/8)^-0.5

// device-global scratch (no allocations allowed)
__device__ __nv_bfloat16 g_Qb[BATCH * NQ * DIM];   // SCALE * normalized Q, [b][q][d]
__device__ __nv_bfloat16 g_Kb[BATCH * NK * DIM];   // normalized K, [b][j][dk] (natural)
__device__ __nv_bfloat16 g_VT[BATCH * DIM * NK];   // V bf16 transposed, [b][dv][j]
__device__ float         g_C [BATCH * DIM * DIM];  // G[dv][dk] = sum_j V[j][dv] K[j][dk]
__device__ __nv_bfloat16 g_Cb[BATCH * DIM * DIM];  // bf16 copy of g_C
__device__ float         g_Ksum[BATCH * DIM];      // sum_j kn[j][d]
__device__ float         g_Vsum[BATCH * DIM];      // sum_j v[j][d]

// ---------------------------------------------------------------- helpers
__device__ __forceinline__ uint32_t smem_u32(const void* p) {
    return (uint32_t)__cvta_generic_to_shared(p);
}

#define LDSM_X4(r0, r1, r2, r3, addr)                                              \
    asm volatile("ldmatrix.sync.aligned.m8n8.x4.shared.b16 {%0,%1,%2,%3},[%4];"    \
                 : "=r"(r0), "=r"(r1), "=r"(r2), "=r"(r3) : "r"(addr))

#define LDSM_X4_T(r0, r1, r2, r3, addr)                                                 \
    asm volatile("ldmatrix.sync.aligned.m8n8.x4.trans.shared.b16 {%0,%1,%2,%3},[%4];"   \
                 : "=r"(r0), "=r"(r1), "=r"(r2), "=r"(r3) : "r"(addr))

#define MMA16816(d, a0, a1, a2, a3, b0, b1)                                        \
    asm volatile("mma.sync.aligned.m16n8k16.row.col.f32.bf16.bf16.f32 "            \
                 "{%0,%1,%2,%3},{%4,%5,%6,%7},{%8,%9},{%0,%1,%2,%3};"              \
                 : "+f"(d[0]), "+f"(d[1]), "+f"(d[2]), "+f"(d[3])                  \
                 : "r"(a0), "r"(a1), "r"(a2), "r"(a3), "r"(b0), "r"(b1))

__device__ __forceinline__ void cp16(uint32_t s, const void* g) {
    asm volatile("cp.async.cg.shared.global [%0], [%1], 16;" :: "r"(s), "l"(g));
}
#define CP_COMMIT() asm volatile("cp.async.commit_group;" ::: "memory")
#define CP_WAIT(n)  asm volatile("cp.async.wait_group %0;" :: "n"(n) : "memory")

// ---------------------------------------------------------------- init
__global__ void zero_kernel() {
    int i = blockIdx.x * 256 + threadIdx.x;           // grid 1032*256 = 264192
    if (i < BATCH * DIM * DIM) g_C[i] = 0.0f;
    else if (i < BATCH * DIM * DIM + BATCH * DIM) g_Ksum[i - BATCH * DIM * DIM] = 0.0f;
    else g_Vsum[i - BATCH * DIM * DIM - BATCH * DIM] = 0.0f;
}

// ---------------------------------------------------------------- fused prep
// blocks [0,2048): Q normalize (x SCALE), 8 rows/block (warp per row)
// blocks [2048,4096): K normalize + Ksum, 8 rows/block
// blocks [4096,4608): V transpose (smem-free) + Vsum, 64 keys x 128 dims/block
__global__ void __launch_bounds__(256)
prep_kernel(const float* __restrict__ q, const float* __restrict__ k,
            const float* __restrict__ v) {
    __shared__ float sSum[256];
    const int bx = blockIdx.x;
    const int tid = threadIdx.x, lane = tid & 31, wid = tid >> 5;

    if (bx < 2048) {
        // ---- Q normalize ----
        int row = bx * 8 + wid;
        const float4* p = (const float4*)(q + (size_t)row * DIM);
        float4 v0 = p[lane], v1 = p[lane + 32];
        float ss = v0.x * v0.x + v0.y * v0.y + v0.z * v0.z + v0.w * v0.w
                 + v1.x * v1.x + v1.y * v1.y + v1.z * v1.z + v1.w * v1.w;
#pragma unroll
        for (int off = 16; off > 0; off >>= 1) ss += __shfl_xor_sync(0xffffffffu, ss, off);
        float sc = SCALE / fmaxf(sqrtf(ss), 1e-12f);
        __nv_bfloat162* drow = (__nv_bfloat162*)(g_Qb + (size_t)row * DIM);
        drow[lane * 2 + 0]      = __floats2bfloat162_rn(v0.x * sc, v0.y * sc);
        drow[lane * 2 + 1]      = __floats2bfloat162_rn(v0.z * sc, v0.w * sc);
        drow[64 + lane * 2 + 0] = __floats2bfloat162_rn(v1.x * sc, v1.y * sc);
        drow[64 + lane * 2 + 1] = __floats2bfloat162_rn(v1.z * sc, v1.w * sc);
    } else if (bx < 4096) {
        // ---- K normalize + Ksum ----
        int row = (bx - 2048) * 8 + wid;       // global row = b*NK + j
        int b = row >> 12;
        sSum[tid] = 0.0f;
        __syncthreads();
        const float4* p = (const float4*)(k + (size_t)row * DIM);
        float4 v0 = p[lane], v1 = p[lane + 32];
        float ss = v0.x * v0.x + v0.y * v0.y + v0.z * v0.z + v0.w * v0.w
                 + v1.x * v1.x + v1.y * v1.y + v1.z * v1.z + v1.w * v1.w;
#pragma unroll
        for (int off = 16; off > 0; off >>= 1) ss += __shfl_xor_sync(0xffffffffu, ss, off);
        float sc = 1.0f / fmaxf(sqrtf(ss), 1e-12f);
        float n0 = v0.x * sc, n1 = v0.y * sc, n2 = v0.z * sc, n3 = v0.w * sc;
        float n4 = v1.x * sc, n5 = v1.y * sc, n6 = v1.z * sc, n7 = v1.w * sc;
        __nv_bfloat162* drow = (__nv_bfloat162*)(g_Kb + (size_t)row * DIM);
        drow[lane * 2 + 0]      = __floats2bfloat162_rn(n0, n1);
        drow[lane * 2 + 1]      = __floats2bfloat162_rn(n2, n3);
        drow[64 + lane * 2 + 0] = __floats2bfloat162_rn(n4, n5);
        drow[64 + lane * 2 + 1] = __floats2bfloat162_rn(n6, n7);
        atomicAdd(&sSum[lane * 4 + 0], n0);
        atomicAdd(&sSum[lane * 4 + 1], n1);
        atomicAdd(&sSum[lane * 4 + 2], n2);
        atomicAdd(&sSum[lane * 4 + 3], n3);
        atomicAdd(&sSum[128 + lane * 4 + 0], n4);
        atomicAdd(&sSum[128 + lane * 4 + 1], n5);
        atomicAdd(&sSum[128 + lane * 4 + 2], n6);
        atomicAdd(&sSum[128 + lane * 4 + 3], n7);
        __syncthreads();
        atomicAdd(&g_Ksum[b * DIM + tid], sSum[tid]);
    } else {
        // ---- V transpose (smem-free writes) + Vsum ----
        int idx = bx - 4096;                   // 0..511
        int b = idx >> 7, rem = idx & 127;
        int dh = rem >> 6, kblk = rem & 63;
        int k0 = kblk * 64;
        int c4 = tid & 31;                     // float4 col: dims dh*128 + c4*4 ..+3
        int r0 = tid >> 5;                     // key chunk: keys r0*8 .. +7
        sSum[tid] = 0.0f;
        __syncthreads();
        float4 x[8];
#pragma unroll
        for (int j = 0; j < 8; j++)
            x[j] = ((const float4*)(v + (size_t)(b * NK + k0 + r0 * 8 + j) * DIM))[dh * 32 + c4];
        float s0 = 0, s1 = 0, s2 = 0, s3 = 0;
#pragma unroll
        for (int j = 0; j < 8; j++) { s0 += x[j].x; s1 += x[j].y; s2 += x[j].z; s3 += x[j].w; }
        // pack: for each dim, 8 keys -> uint4 of bf16
        uint4 w0, w1, w2, w3;
        {
            __nv_bfloat162 t;
#define PK(comp, W)                                                                   \
            t = __floats2bfloat162_rn(x[0].comp, x[1].comp); W.x = *(uint32_t*)&t;    \
            t = __floats2bfloat162_rn(x[2].comp, x[3].comp); W.y = *(uint32_t*)&t;    \
            t = __floats2bfloat162_rn(x[4].comp, x[5].comp); W.z = *(uint32_t*)&t;    \
            t = __floats2bfloat162_rn(x[6].comp, x[7].comp); W.w = *(uint32_t*)&t;
            PK(x, w0) PK(y, w1) PK(z, w2) PK(w, w3)
#undef PK
        }
        const int d0 = dh * 128 + c4 * 4;
        __nv_bfloat16* vt = g_VT + (size_t)(b * DIM + d0) * NK + k0 + r0 * 8;
        *(uint4*)(vt)             = w0;
        *(uint4*)(vt + NK)        = w1;
        *(uint4*)(vt + 2 * NK)    = w2;
        *(uint4*)(vt + 3 * NK)    = w3;
        atomicAdd(&sSum[c4 * 4 + 0], s0);
        atomicAdd(&sSum[c4 * 4 + 1], s1);
        atomicAdd(&sSum[c4 * 4 + 2], s2);
        atomicAdd(&sSum[c4 * 4 + 3], s3);
        __syncthreads();
        if (tid < 128) atomicAdd(&g_Vsum[b * DIM + dh * 128 + tid], sSum[tid]);
    }
}

// ---------------------------------------------------------------- GEMM1: G[dv][dk] += V^T * K (over key slab)
// A = g_VT [dv][j] (non-trans LDSM), B = g_Kb [j][dk] (trans LDSM, R10 PV pattern)
// grid (16 ksplit, 2 mhalf, 4 batch), 256 thr, smem 192KB
extern "C" __global__ void __launch_bounds__(256, 1)
gemm1_kernel() {
    extern __shared__ __align__(128) char smem[];
    const uint32_t sb = smem_u32(smem);
    const int ksp = blockIdx.x, mh = blockIdx.y, b = blockIdx.z;
    const int j0 = ksp * 256;
    const int tid = threadIdx.x, lane = tid & 31, wid = tid >> 5;
    const int m0 = (wid >> 2) * 64, n0 = (wid & 3) * 64;
    const int g = lane >> 3, xs = lane & 7;

    const char* srcA = (const char*)g_VT + (size_t)((b * DIM + mh * 128) * (size_t)NK + j0) * 2;
    const char* srcB = (const char*)g_Kb + (size_t)(b * NK + j0) * DIM * 2;
    for (int i = tid; i < 4096; i += 256) {        // A: 128 dv rows x 512B of j
        int r = i >> 5, c = i & 31;
        cp16(sb + r * 512 + ((c ^ (r & 7)) * 16), srcA + (size_t)r * (NK * 2) + c * 16);
    }
    for (int i = tid; i < 8192; i += 256) {        // B: 256 j rows x 512B of dk
        int r = i >> 5, c = i & 31;
        cp16(sb + 65536u + r * 512 + ((c ^ (r & 7)) * 16), srcB + (size_t)r * 512 + c * 16);
    }
    CP_COMMIT(); CP_WAIT(0); __syncthreads();

    float acc[32][4];
#pragma unroll
    for (int a = 0; a < 32; a++)
#pragma unroll
        for (int j = 0; j < 4; j++) acc[a][j] = 0.0f;

    const uint32_t aBase = sb + (uint32_t)((m0 + (lane & 15)) * 512);
    const int ach = lane >> 4;
    // trans-B: rows j = ks*16 + (g&1)*8 + (lane&7); col chunk cc = n0/8 + nt*2 + (g>>1)
    const uint32_t bBaseT = sb + 65536u + (uint32_t)(((g & 1) * 8 + (lane & 7)) * 512);
    const int ccBase = (n0 >> 3) + (g >> 1);

#pragma unroll
    for (int ks = 0; ks < 16; ks++) {
        uint32_t A[4][4];
        const uint32_t aoff = (uint32_t)(((ks * 2 + ach) ^ xs) * 16);
#pragma unroll
        for (int mt = 0; mt < 4; mt++)
            LDSM_X4(A[mt][0], A[mt][1], A[mt][2], A[mt][3], aBase + mt * 16 * 512 + aoff);
        const uint32_t brow = bBaseT + (uint32_t)(ks * 16 * 512);
#pragma unroll
        for (int nt = 0; nt < 4; nt++) {
            uint32_t b0, b1, b2, b3;
            LDSM_X4_T(b0, b1, b2, b3, brow + (uint32_t)((((ccBase + nt * 2)) ^ xs) * 16));
#pragma unroll
            for (int mt = 0; mt < 4; mt++) {
                MMA16816(acc[mt * 8 + nt * 2],     A[mt][0], A[mt][1], A[mt][2], A[mt][3], b0, b1);
                MMA16816(acc[mt * 8 + nt * 2 + 1], A[mt][0], A[mt][1], A[mt][2], A[mt][3], b2, b3);
            }
        }
    }

    float* Cb = g_C + (size_t)(b * DIM + mh * 128) * DIM;
#pragma unroll
    for (int mt = 0; mt < 4; mt++) {
#pragma unroll
        for (int nt = 0; nt < 4; nt++) {
#pragma unroll
            for (int h = 0; h < 2; h++) {
                float* a4 = acc[mt * 8 + nt * 2 + h];
                int row = m0 + mt * 16 + (lane >> 2);
                int col = n0 + nt * 16 + h * 8 + (lane & 3) * 2;
                atomicAdd(&Cb[(size_t)row * DIM + col],     a4[0]);
                atomicAdd(&Cb[(size_t)row * DIM + col + 1], a4[1]);
                atomicAdd(&Cb[(size_t)(row + 8) * DIM + col],     a4[2]);
                atomicAdd(&Cb[(size_t)(row + 8) * DIM + col + 1], a4[3]);
            }
        }
    }
}

// ---------------------------------------------------------------- convert C -> bf16
__global__ void convc_kernel() {
    int i = blockIdx.x * 256 + threadIdx.x;   // grid 1024*256
    g_Cb[i] = __float2bfloat16(g_C[i]);
}

// ---------------------------------------------------------------- GEMM2 + epilogue
#define G2_SQ   0u
#define G2_SG   65536u
#define G2_SVS  196608u
#define G2_SKS  197632u
#define G2_SDP  198656u
#define G2_SDEN 199680u
static const int G2_SMEM = 200192;

extern "C" __global__ void __launch_bounds__(256, 1)
gemm2_kernel(float* __restrict__ out) {
    extern __shared__ __align__(128) char smem[];
    const uint32_t sb = smem_u32(smem);
    const int qt = blockIdx.x, b = blockIdx.y;
    const int q0 = qt * 128;
    const int tid = threadIdx.x, lane = tid & 31, wid = tid >> 5;
    const int rg = wid >> 1, ch = wid & 1;
    const int g = lane >> 3, xs = lane & 7;

    float* sVS  = (float*)(smem + G2_SVS);
    float* sKS  = (float*)(smem + G2_SKS);
    float* sDP  = (float*)(smem + G2_SDP);
    float* sDEN = (float*)(smem + G2_SDEN);

    const char* srcQ = (const char*)g_Qb + (size_t)(b * NQ + q0) * DIM * 2;
    const char* srcG = (const char*)g_Cb + (size_t)b * DIM * DIM * 2;
    for (int i = tid; i < 4096; i += 256) {
        int r = i >> 5, c = i & 31;
        cp16(sb + G2_SQ + r * 512 + ((c ^ (r & 7)) * 16), srcQ + i * 16);
    }
    for (int i = tid; i < 8192; i += 256) {
        int r = i >> 5, c = i & 31;
        cp16(sb + G2_SG + r * 512 + ((c ^ (r & 7)) * 16), srcG + i * 16);
    }
    if (tid < DIM) { sVS[tid] = g_Vsum[b * DIM + tid]; sKS[tid] = g_Ksum[b * DIM + tid]; }
    CP_COMMIT(); CP_WAIT(0);
    __syncthreads();

    // denominator partials
    {
        int r = tid >> 1, hh = tid & 1;
        int xr = r & 7;
        float s = 0.0f;
#pragma unroll 16
        for (int i = 0; i < 128; i++) {
            int d = hh * 128 + i;
            uint32_t addr = (uint32_t)(r * 512 + (((d >> 3) ^ xr) * 16) + (d & 7) * 2);
            __nv_bfloat16 qv = *(__nv_bfloat16*)(smem + G2_SQ + addr);
            s += __bfloat162float(qv) * sKS[d];
        }
        sDP[tid] = s;
    }
    __syncthreads();
    if (tid < 128) sDEN[tid] = 1.0f / ((float)NK + sDP[2 * tid] + sDP[2 * tid + 1]);
    __syncthreads();

    float acc[32][4];
#pragma unroll
    for (int a = 0; a < 32; a++)
#pragma unroll
        for (int j = 0; j < 4; j++) acc[a][j] = 0.0f;

    const uint32_t aBase = sb + G2_SQ + (uint32_t)((rg * 32 + (lane & 15)) * 512);
    const uint32_t bBase = sb + G2_SG + (uint32_t)((ch * 128 + (g >> 1) * 8 + (lane & 7)) * 512);
    const int ach = lane >> 4, bch = g & 1;

#pragma unroll
    for (int ks = 0; ks < 16; ks++) {
        uint32_t A[2][4];
        const uint32_t aoff = (uint32_t)(((ks * 2 + ach) ^ xs) * 16);
        LDSM_X4(A[0][0], A[0][1], A[0][2], A[0][3], aBase + aoff);
        LDSM_X4(A[1][0], A[1][1], A[1][2], A[1][3], aBase + 16 * 512 + aoff);
        const uint32_t boff = (uint32_t)(((ks * 2 + bch) ^ xs) * 16);
#pragma unroll
        for (int nt = 0; nt < 8; nt++) {
            uint32_t b0, b1, b2, b3;
            LDSM_X4(b0, b1, b2, b3, bBase + nt * 16 * 512 + boff);
#pragma unroll
            for (int mt = 0; mt < 2; mt++) {
                MMA16816(acc[mt * 16 + nt * 2],     A[mt][0], A[mt][1], A[mt][2], A[mt][3], b0, b1);
                MMA16816(acc[mt * 16 + nt * 2 + 1], A[mt][0], A[mt][1], A[mt][2], A[mt][3], b2, b3);
            }
        }
    }

    float* opb = out + (size_t)(b * NQ + q0) * DIM;
#pragma unroll
    for (int mt = 0; mt < 2; mt++) {
        const int r1 = rg * 32 + mt * 16 + (lane >> 2);
        const float inv1 = sDEN[r1];
        const float inv2 = sDEN[r1 + 8];
        float* op = opb + (size_t)r1 * DIM;
#pragma unroll
        for (int j8 = 0; j8 < 16; j8++) {
            const int c = ch * 128 + j8 * 8 + 2 * (lane & 3);
            float vs0 = sVS[c], vs1 = sVS[c + 1];
            float* a4 = acc[mt * 16 + j8];
            *(float2*)(op + c) =
                make_float2((vs0 + a4[0]) * inv1, (vs1 + a4[1]) * inv1);
            *(float2*)(op + 8 * DIM + c) =
                make_float2((vs0 + a4[2]) * inv2, (vs1 + a4[3]) * inv2);
        }
    }
}

// ---------------------------------------------------------------- launch
extern "C" void kernel_launch(void* const* d_in, const int* in_sizes, int n_in,
                              void* d_out, int out_size) {
    const float* q = (const float*)d_in[0];
    const float* k = (const float*)d_in[1];
    const float* v = (const float*)d_in[2];
    float* out = (float*)d_out;

    cudaFuncSetAttribute(gemm1_kernel, cudaFuncAttributeMaxDynamicSharedMemorySize, 196608);
    cudaFuncSetAttribute(gemm2_kernel, cudaFuncAttributeMaxDynamicSharedMemorySize, G2_SMEM);

    zero_kernel<<<1032, 256>>>();
    prep_kernel<<<4608, 256>>>(q, k, v);
    gemm1_kernel<<<dim3(16, 2, BATCH), 256, 196608>>>();
    convc_kernel<<<1024, 256>>>();
    gemm2_kernel<<<dim3(NQ / 128, BATCH), 256, G2_SMEM>>>(out);
}